// round 7
// baseline (speedup 1.0000x reference)
#include <cuda_runtime.h>
#include <stdint.h>

// Problem constants (fixed by the reference)
#define N_POI   10000
#define V_VOCAB 20000
#define BS      6400          // B*S = 64*100
#define N_VEC   (N_POI / 4)   // 2500 float4 per row
#define BIG_INV (1.0f / 9999999.99f)

// Persistent grid: 148 SMs x 8 blocks/SM (256 thr, 32 regs -> 8 CTA/SM)
#define GRID_P  1184

__device__ __forceinline__ float4 recip_mask(float4 v) {
    float4 o;
    o.x = (v.x == 0.0f) ? BIG_INV : __fdividef(1.0f, v.x);
    o.y = (v.y == 0.0f) ? BIG_INV : __fdividef(1.0f, v.y);
    o.z = (v.z == 0.0f) ? BIG_INV : __fdividef(1.0f, v.z);
    o.w = (v.w == 0.0f) ? BIG_INV : __fdividef(1.0f, v.w);
    return o;
}

// Resolve venueid2coor[inputs_poi[orow]] -> matrix row. Broadcast loads
// (same address across the warp) -> 1 transaction, L2-hot after wave 1.
__device__ __forceinline__ int resolve_row(const void* __restrict__ v2c,
                                           const void* __restrict__ poi,
                                           int orow, bool is64) {
    if (is64) {
        long long vid = ((const long long*)poi)[orow];
        return (int)((const long long*)v2c)[vid];
    } else {
        int vid = ((const int*)poi)[orow];
        return ((const int*)v2c)[vid];
    }
}

// ---------------------------------------------------------------------------
// Persistent fused kernel: grid-stride over output rows, one wave.
//   - index dtype auto-detected once (int64 LE values in [0,10000) have zero
//     upper words; 16 consecutive zeros on int32 data has prob ~1e-64)
//   - next row's index prefetched before streaming the current row, so the
//     two dependent gather-index loads never expose latency
//   - no barriers, no smem; 4 independent float4 loads in flight/iteration
//   - __ldcs reads (no in-SM reuse), __stcs writes (never re-read)
// ---------------------------------------------------------------------------
__global__ void __launch_bounds__(256)
fused_gather_recip(const void* __restrict__ v2c,
                   const void* __restrict__ poi,
                   const float* __restrict__ mat,
                   float* __restrict__ out) {
    // dtype detection (once per thread; all loads L1/L2-broadcast)
    bool is64 = true;
    {
        const unsigned long long* p = (const unsigned long long*)v2c;
        #pragma unroll
        for (int i = 0; i < 16; i++)
            if ((p[i] >> 32) != 0ull) { is64 = false; break; }
    }

    int orow = blockIdx.x;
    if (orow >= BS) return;
    int srow = resolve_row(v2c, poi, orow, is64);

    while (true) {
        // Prefetch next row's gather index before streaming this row:
        // its dependent-load latency hides under the 40KB stream below.
        const int onext = orow + GRID_P;
        int srow_next = 0;
        if (onext < BS) srow_next = resolve_row(v2c, poi, onext, is64);

        const float4* __restrict__ src =
            (const float4*)(mat + (long long)srow * N_POI);
        float4* __restrict__ dst =
            (float4*)(out + (long long)orow * N_POI);

        // N_VEC = 2500 = 2*1024 + 452
        #pragma unroll
        for (int base = 0; base < 2048; base += 1024) {
            const int c = base + threadIdx.x;
            float4 v0 = __ldcs(&src[c]);
            float4 v1 = __ldcs(&src[c + 256]);
            float4 v2 = __ldcs(&src[c + 512]);
            float4 v3 = __ldcs(&src[c + 768]);
            __stcs(&dst[c],       recip_mask(v0));
            __stcs(&dst[c + 256], recip_mask(v1));
            __stcs(&dst[c + 512], recip_mask(v2));
            __stcs(&dst[c + 768], recip_mask(v3));
        }
        {
            const int c0 = 2048 + threadIdx.x;   // < 2304, always valid
            const int c1 = c0 + 256;
            const bool p1 = (c1 < N_VEC);
            float4 v0 = __ldcs(&src[c0]);
            float4 v1;
            if (p1) v1 = __ldcs(&src[c1]);
            __stcs(&dst[c0], recip_mask(v0));
            if (p1) __stcs(&dst[c1], recip_mask(v1));
        }

        if (onext >= BS) break;
        orow = onext;
        srow = srow_next;
    }
}

// ---------------------------------------------------------------------------
// Input order (setup_inputs dict order):
//   d_in[0] = venueid2coor        [V_VOCAB]       int64/int32 (detected)
//   d_in[1] = inputs_poi          [B*S]           int64/int32 (same dtype)
//   d_in[2] = poi_distance_matrix [N_POI*N_POI]   float32
// out: [B, S, N_POI] float32
// ---------------------------------------------------------------------------
extern "C" void kernel_launch(void* const* d_in, const int* in_sizes, int n_in,
                              void* d_out, int out_size) {
    const void*  v2c = d_in[0];
    const void*  poi = d_in[1];
    const float* mat = (const float*)d_in[2];
    float*       out = (float*)d_out;

    fused_gather_recip<<<GRID_P, 256>>>(v2c, poi, mat, out);
}